// round 2
// baseline (speedup 1.0000x reference)
#include <cuda_runtime.h>

#define NN    50000
#define EE    800000
#define NGMAX 64
#define KP1   648     // 256+256+128+deg+1 = 642 -> pad to mult of 8
#define KP2   328     // 128+128+64+1 = 321 -> pad
#define ACAP  24000
#define E2CAP 4000

// ---------------- device scratch ----------------
__device__ unsigned char g_needX1[NN], g_needX2[NN], g_needX3[NN];
__device__ unsigned char g_eL2[EE], g_eL3[EE], g_eE1[EE];
__device__ int g_cnt[8];  // 0:L1e 1:E1e 2:L2e 3:L3e 4:X1n 5:X2n 6:ngraphs
__device__ int g_eListL1[EE], g_eListE1[ACAP], g_eListL2[ACAP], g_eListL3[E2CAP];
__device__ int g_e1pos[EE];
__device__ int g_nX1[ACAP], g_nX2[ACAP], g_outNode[NGMAX];

__device__ float g_sx1[NN * 256];
__device__ float g_sea1[NN * 128];
__device__ float g_deg1[NN];
__device__ float g_x1r[NN * 128];
__device__ float g_e1r[ACAP * 64];
__device__ float g_sx2[NN * 128], g_se2[NN * 64];
__device__ float g_x2r[NN * 128];
__device__ float g_e2r[E2CAP * 64];
__device__ float g_sx3[NN * 128], g_se3[NN * 64];
__device__ float g_Acat[ACAP * KP1];
__device__ float g_W1n[KP1 * 128], g_W1e[KP1 * 64];
__device__ float g_W2n[KP2 * 128], g_W2e[KP2 * 64];
__device__ float g_W3[KP2 * 256];

// ---------------- helpers ----------------
__device__ __forceinline__ int warp_push(int* list, int* cnt, bool flag, int val, int cap) {
    unsigned bal = __ballot_sync(0xffffffffu, flag);
    int pos = -1;
    if (bal) {
        int lane = threadIdx.x & 31;
        int leader = __ffs(bal) - 1;
        int base = 0;
        if (lane == leader) base = atomicAdd(cnt, __popc(bal));
        base = __shfl_sync(0xffffffffu, base, leader);
        if (flag) {
            pos = base + __popc(bal & ((1u << lane) - 1u));
            if (pos < cap) list[pos] = val;
        }
    }
    return pos;
}

// ---------------- marking ----------------
__global__ void k_init(int n_graphs) {
    int i = blockIdx.x * blockDim.x + threadIdx.x;
    if (i < NN) { g_needX1[i] = 0; g_needX2[i] = 0; g_needX3[i] = 0; }
    if (i < 8) g_cnt[i] = (i == 6) ? n_graphs : 0;
}

__global__ void k_masters(const int* __restrict__ batch) {
    int i = blockIdx.x * blockDim.x + threadIdx.x;
    if (i < NN && (i == 0 || batch[i] != batch[i - 1])) {
        g_outNode[batch[i]] = i;
        g_needX3[i] = 1;
        g_needX2[i] = 1;
    }
}

__global__ void k_passA(const int* __restrict__ src, const int* __restrict__ dst) {
    int e = blockIdx.x * blockDim.x + threadIdx.x;
    if (e < EE) {
        unsigned char f = g_needX3[dst[e]];
        g_eL3[e] = f;
        if (f) g_needX2[src[e]] = 1;
    }
}

__global__ void k_prop() {
    int i = blockIdx.x * blockDim.x + threadIdx.x;
    if (i < NN && g_needX2[i]) g_needX1[i] = 1;
}

__global__ void k_passB(const int* __restrict__ src, const int* __restrict__ dst) {
    int e = blockIdx.x * blockDim.x + threadIdx.x;
    if (e < EE) {
        unsigned char l2 = g_needX2[dst[e]];
        unsigned char l3 = g_eL3[e];
        g_eL2[e] = l2;
        g_eE1[e] = (unsigned char)(l2 | l3);
        if (l2 | l3) g_needX1[src[e]] = 1;
        if (l3)      g_needX1[dst[e]] = 1;
    }
}

__global__ void k_passC(const int* __restrict__ dst) {
    int e = blockIdx.x * blockDim.x + threadIdx.x;  // exact EE coverage (800000 % 256 == 0)
    warp_push(g_eListL1, &g_cnt[0], g_needX1[dst[e]] != 0, e, EE);
    int p = warp_push(g_eListE1, &g_cnt[1], g_eE1[e] != 0, e, ACAP);
    if (p >= 0) g_e1pos[e] = p;
    warp_push(g_eListL2, &g_cnt[2], g_eL2[e] != 0, e, ACAP);
    warp_push(g_eListL3, &g_cnt[3], g_eL3[e] != 0, e, E2CAP);
}

__global__ void k_compactN() {
    int i = blockIdx.x * blockDim.x + threadIdx.x;
    warp_push(g_nX1, &g_cnt[4], (i < NN) && g_needX1[i], i, ACAP);
    warp_push(g_nX2, &g_cnt[5], (i < NN) && g_needX2[i], i, ACAP);
}

__global__ void k_zero() {
    int t0 = blockIdx.x * blockDim.x + threadIdx.x;
    int stride = gridDim.x * blockDim.x;
    int c1 = g_cnt[4]; if (c1 > ACAP) c1 = ACAP;
    for (int t = t0; t < c1 * 256; t += stride) {
        int i = t >> 8, c = t & 255; int n = g_nX1[i];
        g_sx1[(size_t)n * 256 + c] = 0.f;
        if (c < 128) g_sea1[n * 128 + c] = 0.f;
        if (c == 0)  g_deg1[n] = 0.f;
    }
    int c2 = g_cnt[5]; if (c2 > ACAP) c2 = ACAP;
    for (int t = t0; t < c2 * 128; t += stride) {
        int i = t >> 7, c = t & 127; int n = g_nX2[i];
        g_sx2[n * 128 + c] = 0.f;
        if (c < 64) g_se2[n * 64 + c] = 0.f;
    }
    int cg = g_cnt[6];
    for (int t = t0; t < cg * 128; t += stride) {
        int g = t >> 7, c = t & 127; int n = g_outNode[g];
        g_sx3[n * 128 + c] = 0.f;
        if (c < 64) g_se3[n * 64 + c] = 0.f;
    }
}

// ---------------- scatters ----------------
__global__ void k_scatter1(const float* __restrict__ x, const float* __restrict__ ea,
                           const int* __restrict__ src, const int* __restrict__ dst) {
    int warpId = (blockIdx.x * blockDim.x + threadIdx.x) >> 5;
    int lane = threadIdx.x & 31;
    int nw = (gridDim.x * blockDim.x) >> 5;
    int cnt = g_cnt[0];
    for (int idx = warpId; idx < cnt; idx += nw) {
        int e = g_eListL1[idx];
        int s = src[e], d = dst[e];
        const float* xs = x + (size_t)s * 256;
        float* o1 = g_sx1 + (size_t)d * 256;
        #pragma unroll
        for (int c = 0; c < 8; c++) atomicAdd(o1 + lane + 32 * c, xs[lane + 32 * c]);
        const float* er = ea + (size_t)e * 128;
        float* o2 = g_sea1 + (size_t)d * 128;
        #pragma unroll
        for (int c = 0; c < 4; c++) atomicAdd(o2 + lane + 32 * c, er[lane + 32 * c]);
        if (lane == 0) atomicAdd(&g_deg1[d], 1.0f);
    }
}

__global__ void k_scatter2(const int* __restrict__ src, const int* __restrict__ dst) {
    int warpId = (blockIdx.x * blockDim.x + threadIdx.x) >> 5;
    int lane = threadIdx.x & 31;
    int nw = (gridDim.x * blockDim.x) >> 5;
    int cnt = g_cnt[2]; if (cnt > ACAP) cnt = ACAP;
    for (int idx = warpId; idx < cnt; idx += nw) {
        int e = g_eListL2[idx];
        int s = src[e], d = dst[e];
        int ep = g_e1pos[e];
        #pragma unroll
        for (int c = 0; c < 4; c++)
            atomicAdd(&g_sx2[d * 128 + lane + 32 * c], g_x1r[s * 128 + lane + 32 * c]);
        #pragma unroll
        for (int c = 0; c < 2; c++)
            atomicAdd(&g_se2[d * 64 + lane + 32 * c], g_e1r[(size_t)ep * 64 + lane + 32 * c]);
    }
}

__global__ void k_scatter3(const int* __restrict__ src, const int* __restrict__ dst) {
    int warpId = (blockIdx.x * blockDim.x + threadIdx.x) >> 5;
    int lane = threadIdx.x & 31;
    int nw = (gridDim.x * blockDim.x) >> 5;
    int cnt = g_cnt[3]; if (cnt > E2CAP) cnt = E2CAP;
    for (int idx = warpId; idx < cnt; idx += nw) {
        int e = g_eListL3[idx];
        int s = src[e], d = dst[e];
        #pragma unroll
        for (int c = 0; c < 4; c++)
            atomicAdd(&g_sx3[d * 128 + lane + 32 * c], g_x2r[s * 128 + lane + 32 * c]);
        #pragma unroll
        for (int c = 0; c < 2; c++)
            atomicAdd(&g_se3[d * 64 + lane + 32 * c], g_e2r[idx * 64 + lane + 32 * c]);
    }
}

// ---------------- weight pre-combination ----------------
__global__ void k_buildW1n(const float* __restrict__ ws1, const float* __restrict__ wmx1,
                           const float* __restrict__ wme1, const float* __restrict__ wproj,
                           const float* __restrict__ bproj, const float* __restrict__ bs1) {
    int t = blockIdx.x * blockDim.x + threadIdx.x;
    if (t >= KP1 * 128) return;
    int k = t >> 7, j = t & 127;
    float v = 0.f;
    if (k < 256) v = ws1[k * 128 + j];
    else if (k < 512) v = wmx1[(k - 256) * 128 + j];
    else if (k < 640) { int p = k - 512; float s = 0.f;
        for (int q = 0; q < 64; q++) s += wproj[p * 64 + q] * wme1[q * 128 + j]; v = s; }
    else if (k == 640) { float s = 0.f;
        for (int q = 0; q < 64; q++) s += bproj[q] * wme1[q * 128 + j]; v = s; }
    else if (k == 641) v = bs1[j];
    g_W1n[t] = v;
}

__global__ void k_buildW1e(const float* __restrict__ wes1, const float* __restrict__ wed1,
                           const float* __restrict__ wee1, const float* __restrict__ wproj,
                           const float* __restrict__ bproj, const float* __restrict__ be1) {
    int t = blockIdx.x * blockDim.x + threadIdx.x;
    if (t >= KP1 * 64) return;
    int k = t >> 6, j = t & 63;
    float v = 0.f;
    if (k < 256) v = wes1[k * 64 + j];
    else if (k < 512) v = wed1[(k - 256) * 64 + j];
    else if (k < 640) { int p = k - 512; float s = 0.f;
        for (int q = 0; q < 64; q++) s += wproj[p * 64 + q] * wee1[q * 64 + j]; v = s; }
    else if (k == 640) { float s = 0.f;
        for (int q = 0; q < 64; q++) s += bproj[q] * wee1[q * 64 + j]; v = s + be1[j]; }
    g_W1e[t] = v;
}

__global__ void k_buildW2n(const float* __restrict__ ws2, const float* __restrict__ wmx2,
                           const float* __restrict__ wme2, const float* __restrict__ bs2) {
    int t = blockIdx.x * blockDim.x + threadIdx.x;
    if (t >= KP2 * 128) return;
    int k = t >> 7, j = t & 127;
    float v = 0.f;
    if (k < 128) v = ws2[k * 128 + j];
    else if (k < 256) v = wmx2[(k - 128) * 128 + j];
    else if (k < 320) v = wme2[(k - 256) * 128 + j];
    else if (k == 320) v = bs2[j];
    g_W2n[t] = v;
}

__global__ void k_buildW2e(const float* __restrict__ wes2, const float* __restrict__ wed2,
                           const float* __restrict__ wee2, const float* __restrict__ be2) {
    int t = blockIdx.x * blockDim.x + threadIdx.x;
    if (t >= KP2 * 64) return;
    int k = t >> 6, j = t & 63;
    float v = 0.f;
    if (k < 128) v = wes2[k * 64 + j];
    else if (k < 256) v = wed2[(k - 128) * 64 + j];
    else if (k < 320) v = wee2[(k - 256) * 64 + j];
    else if (k == 320) v = be2[j];
    g_W2e[t] = v;
}

__global__ void k_buildW3(const float* __restrict__ ws3, const float* __restrict__ wmx3,
                          const float* __restrict__ wme3, const float* __restrict__ bs3) {
    int t = blockIdx.x * blockDim.x + threadIdx.x;
    if (t >= KP2 * 256) return;
    int k = t >> 8, j = t & 255;
    float v = 0.f;
    if (k < 128) v = ws3[k * 256 + j];
    else if (k < 256) v = wmx3[(k - 128) * 256 + j];
    else if (k < 320) v = wme3[(k - 256) * 256 + j];
    else if (k == 320) v = bs3[j];
    g_W3[t] = v;
}

// ---------------- A-matrix gathers (one block per row) ----------------
__global__ void k_gatherN1(const float* __restrict__ x) {
    int cnt = g_cnt[4]; if (cnt > ACAP) cnt = ACAP;
    for (int i = blockIdx.x; i < cnt; i += gridDim.x) {
        int n = g_nX1[i];
        float* A = g_Acat + (size_t)i * KP1;
        for (int k = threadIdx.x; k < KP1; k += blockDim.x) {
            float v;
            if (k < 256) v = x[(size_t)n * 256 + k];
            else if (k < 512) v = g_sx1[(size_t)n * 256 + (k - 256)];
            else if (k < 640) v = g_sea1[n * 128 + (k - 512)];
            else if (k == 640) v = g_deg1[n];
            else if (k == 641) v = 1.f;
            else v = 0.f;
            A[k] = v;
        }
    }
}

__global__ void k_gatherE1(const float* __restrict__ x, const float* __restrict__ ea,
                           const int* __restrict__ src, const int* __restrict__ dst) {
    int cnt = g_cnt[1]; if (cnt > ACAP) cnt = ACAP;
    for (int i = blockIdx.x; i < cnt; i += gridDim.x) {
        int e = g_eListE1[i];
        int s = src[e], d = dst[e];
        float* A = g_Acat + (size_t)i * KP1;
        for (int k = threadIdx.x; k < KP1; k += blockDim.x) {
            float v;
            if (k < 256) v = x[(size_t)s * 256 + k];
            else if (k < 512) v = x[(size_t)d * 256 + (k - 256)];
            else if (k < 640) v = ea[(size_t)e * 128 + (k - 512)];
            else if (k == 640) v = 1.f;
            else v = 0.f;
            A[k] = v;
        }
    }
}

__global__ void k_gatherN2() {
    int cnt = g_cnt[5]; if (cnt > ACAP) cnt = ACAP;
    for (int i = blockIdx.x; i < cnt; i += gridDim.x) {
        int n = g_nX2[i];
        float* A = g_Acat + (size_t)i * KP2;
        for (int k = threadIdx.x; k < KP2; k += blockDim.x) {
            float v;
            if (k < 128) v = g_x1r[n * 128 + k];
            else if (k < 256) v = g_sx2[n * 128 + (k - 128)];
            else if (k < 320) v = g_se2[n * 64 + (k - 256)];
            else if (k == 320) v = 1.f;
            else v = 0.f;
            A[k] = v;
        }
    }
}

__global__ void k_gatherE2(const int* __restrict__ src, const int* __restrict__ dst) {
    int cnt = g_cnt[3]; if (cnt > E2CAP) cnt = E2CAP;
    for (int i = blockIdx.x; i < cnt; i += gridDim.x) {
        int e = g_eListL3[i];
        int s = src[e], d = dst[e];
        int ep = g_e1pos[e];
        float* A = g_Acat + (size_t)i * KP2;
        for (int k = threadIdx.x; k < KP2; k += blockDim.x) {
            float v;
            if (k < 128) v = g_x1r[s * 128 + k];
            else if (k < 256) v = g_x1r[d * 128 + (k - 128)];
            else if (k < 320) v = g_e1r[(size_t)ep * 64 + (k - 256)];
            else if (k == 320) v = 1.f;
            else v = 0.f;
            A[k] = v;
        }
    }
}

__global__ void k_gatherF() {
    int cnt = g_cnt[6];
    for (int g = blockIdx.x; g < cnt; g += gridDim.x) {
        int n = g_outNode[g];
        float* A = g_Acat + (size_t)g * KP2;
        for (int k = threadIdx.x; k < KP2; k += blockDim.x) {
            float v;
            if (k < 128) v = g_x2r[n * 128 + k];
            else if (k < 256) v = g_sx3[n * 128 + (k - 128)];
            else if (k < 320) v = g_se3[n * 64 + (k - 256)];
            else if (k == 320) v = 1.f;
            else v = 0.f;
            A[k] = v;
        }
    }
}

// ---------------- tiled GEMM: Out[dest?dest[i]:i] = relu?(Acat[i,:] @ W) ----------------
template <int KP, int N, bool RELU>
__global__ void k_gemm(const float* __restrict__ W, float* __restrict__ Out,
                       const int* __restrict__ dest, int cidx, int cap) {
    constexpr int CN = N / 32;
    __shared__ float sA[64][8];
    __shared__ float sW[8][N];
    int M = g_cnt[cidx]; if (M > cap) M = cap;
    const int trow = threadIdx.x >> 5, tcol = threadIdx.x & 31;
    for (int mt = blockIdx.x; mt * 64 < M; mt += gridDim.x) {
        const int m0 = mt * 64;
        float acc[8][CN];
        #pragma unroll
        for (int r = 0; r < 8; r++)
            #pragma unroll
            for (int c = 0; c < CN; c++) acc[r][c] = 0.f;

        for (int k0 = 0; k0 < KP; k0 += 8) {
            __syncthreads();
            #pragma unroll
            for (int i = threadIdx.x; i < 512; i += 256) {
                int r = i >> 3, kk = i & 7;
                int ar = m0 + r;
                sA[r][kk] = (ar < M) ? g_Acat[(size_t)ar * KP + k0 + kk] : 0.f;
            }
            #pragma unroll
            for (int i = threadIdx.x; i < 8 * N; i += 256)
                sW[i / N][i % N] = W[(k0 + i / N) * N + (i % N)];
            __syncthreads();
            #pragma unroll
            for (int kk = 0; kk < 8; kk++) {
                float a[8], b[CN];
                #pragma unroll
                for (int r = 0; r < 8; r++) a[r] = sA[trow * 8 + r][kk];
                #pragma unroll
                for (int c = 0; c < CN; c++) b[c] = sW[kk][tcol + 32 * c];
                #pragma unroll
                for (int r = 0; r < 8; r++)
                    #pragma unroll
                    for (int c = 0; c < CN; c++)
                        acc[r][c] = fmaf(a[r], b[c], acc[r][c]);
            }
        }
        #pragma unroll
        for (int r = 0; r < 8; r++) {
            int row = m0 + trow * 8 + r;
            if (row < M) {
                int drow = dest ? dest[row] : row;
                #pragma unroll
                for (int c = 0; c < CN; c++) {
                    float v = acc[r][c];
                    if (RELU) v = fmaxf(v, 0.f);
                    Out[(size_t)drow * N + tcol + 32 * c] = v;
                }
            }
        }
        __syncthreads();
    }
}

// ---------------- host ----------------
extern "C" void kernel_launch(void* const* d_in, const int* in_sizes, int n_in,
                              void* d_out, int out_size) {
    const float* x     = (const float*)d_in[0];
    const int*   ei    = (const int*)d_in[1];
    const int*   src   = ei;
    const int*   dst   = ei + EE;
    const float* ea    = (const float*)d_in[2];
    const int*   batch = (const int*)d_in[3];
    const float* wproj = (const float*)d_in[4];
    const float* bproj = (const float*)d_in[5];
    const float* ws1 = (const float*)d_in[6],  *bs1 = (const float*)d_in[7];
    const float* wmx1 = (const float*)d_in[8], *wme1 = (const float*)d_in[9];
    const float* wes1 = (const float*)d_in[10], *wed1 = (const float*)d_in[11];
    const float* wee1 = (const float*)d_in[12], *be1 = (const float*)d_in[13];
    const float* ws2 = (const float*)d_in[14], *bs2 = (const float*)d_in[15];
    const float* wmx2 = (const float*)d_in[16], *wme2 = (const float*)d_in[17];
    const float* wes2 = (const float*)d_in[18], *wed2 = (const float*)d_in[19];
    const float* wee2 = (const float*)d_in[20], *be2 = (const float*)d_in[21];
    const float* ws3 = (const float*)d_in[22], *bs3 = (const float*)d_in[23];
    const float* wmx3 = (const float*)d_in[24], *wme3 = (const float*)d_in[25];
    float* out = (float*)d_out;
    int n_graphs = out_size / 256;

    float *W1n, *W1e, *W2n, *W2e, *W3, *x1r, *e1r, *x2r, *e2r;
    int *nX1, *nX2;
    cudaGetSymbolAddress((void**)&W1n, g_W1n);
    cudaGetSymbolAddress((void**)&W1e, g_W1e);
    cudaGetSymbolAddress((void**)&W2n, g_W2n);
    cudaGetSymbolAddress((void**)&W2e, g_W2e);
    cudaGetSymbolAddress((void**)&W3,  g_W3);
    cudaGetSymbolAddress((void**)&x1r, g_x1r);
    cudaGetSymbolAddress((void**)&e1r, g_e1r);
    cudaGetSymbolAddress((void**)&x2r, g_x2r);
    cudaGetSymbolAddress((void**)&e2r, g_e2r);
    cudaGetSymbolAddress((void**)&nX1, g_nX1);
    cudaGetSymbolAddress((void**)&nX2, g_nX2);

    const int NB_N = (NN + 255) / 256;
    const int NB_E = EE / 256;

    k_init<<<NB_N, 256>>>(n_graphs);
    k_buildW1n<<<(KP1 * 128 + 255) / 256, 256>>>(ws1, wmx1, wme1, wproj, bproj, bs1);
    k_buildW1e<<<(KP1 * 64 + 255) / 256, 256>>>(wes1, wed1, wee1, wproj, bproj, be1);
    k_buildW2n<<<(KP2 * 128 + 255) / 256, 256>>>(ws2, wmx2, wme2, bs2);
    k_buildW2e<<<(KP2 * 64 + 255) / 256, 256>>>(wes2, wed2, wee2, be2);
    k_buildW3 <<<(KP2 * 256 + 255) / 256, 256>>>(ws3, wmx3, wme3, bs3);

    k_masters<<<NB_N, 256>>>(batch);
    k_passA<<<NB_E, 256>>>(src, dst);
    k_prop<<<NB_N, 256>>>();
    k_passB<<<NB_E, 256>>>(src, dst);
    k_passC<<<NB_E, 256>>>(dst);
    k_compactN<<<NB_N, 256>>>();
    k_zero<<<1024, 256>>>();

    // ---- layer 1 ----
    k_scatter1<<<2048, 256>>>(x, ea, src, dst);
    k_gatherN1<<<2048, 256>>>(x);
    k_gemm<KP1, 128, true><<<256, 256>>>(W1n, x1r, nX1, 4, ACAP);
    k_gatherE1<<<2048, 256>>>(x, ea, src, dst);
    k_gemm<KP1, 64, true><<<256, 256>>>(W1e, e1r, (const int*)0, 1, ACAP);

    // ---- layer 2 ----
    k_scatter2<<<512, 256>>>(src, dst);
    k_gatherN2<<<512, 256>>>();
    k_gemm<KP2, 128, true><<<64, 256>>>(W2n, x2r, nX2, 5, ACAP);
    k_gatherE2<<<512, 256>>>(src, dst);
    k_gemm<KP2, 64, true><<<64, 256>>>(W2e, e2r, (const int*)0, 3, E2CAP);

    // ---- layer 3 + output ----
    k_scatter3<<<64, 256>>>(src, dst);
    k_gatherF<<<64, 256>>>();
    k_gemm<KP2, 256, false><<<1, 256>>>(W3, out, (const int*)0, 6, NGMAX);
}

// round 4
// speedup vs baseline: 1.4757x; 1.4757x over previous
#include <cuda_runtime.h>

#define NN    50000
#define EE    800000
#define NGMAX 64
#define KP1   648     // 256(x) + 256(sum x_src) + 128(sum ea) + deg + 1 + pad
#define KP2   328     // 128 + 128 + 64 + 1 + pad
#define ACAP  24000
#define E2CAP 4000

// ---------------- device scratch ----------------
__device__ unsigned char g_needX1[NN], g_needX2[NN], g_needX3[NN];
__device__ int g_cnt[8];   // 1:E1e 2:L2e 3:L3e 4:X1n 5:X2n 6:ngraphs
__device__ int g_eListE1[ACAP], g_eListL2[ACAP], g_eListL3[E2CAP];
__device__ int g_e1pos[EE];
__device__ int g_nX1[ACAP], g_nX2[ACAP], g_outNode[NGMAX], g_invX1[NN];
__device__ int g_csrCnt[ACAP], g_csrOff[ACAP + 1], g_csrCur[ACAP];
__device__ int g_csrE[EE];

__device__ float g_Acat[(size_t)ACAP * KP1];
__device__ float g_x1r[(size_t)NN * 128];
__device__ float g_psd[(size_t)NN * 128];          // [es(64) | ed(64)] per node
__device__ float g_q[(size_t)ACAP * 64];
__device__ float g_e1r[(size_t)ACAP * 64];
__device__ float g_sx2[(size_t)NN * 128], g_se2[(size_t)NN * 64];
__device__ float g_x2r[(size_t)NN * 128];
__device__ float g_e2r[(size_t)E2CAP * 64];
__device__ float g_sx3[(size_t)NN * 128], g_se3[(size_t)NN * 64];

__device__ float g_W1n[KP1 * 128];
__device__ float g_Wpsd[256 * 128];
__device__ float g_Wq[128 * 64];
__device__ float g_Ce1[64];
__device__ float g_W2n[KP2 * 128], g_W2e[KP2 * 64], g_W3[KP2 * 256];

// ---------------- helpers ----------------
__device__ __forceinline__ int warp_push(int* list, int* cnt, bool flag, int val, int cap) {
    unsigned bal = __ballot_sync(0xffffffffu, flag);
    int pos = -1;
    if (bal) {
        int lane = threadIdx.x & 31;
        int leader = __ffs(bal) - 1;
        int base = 0;
        if (lane == leader) base = atomicAdd(cnt, __popc(bal));
        base = __shfl_sync(0xffffffffu, base, leader);
        if (flag) {
            pos = base + __popc(bal & ((1u << lane) - 1u));
            if (pos < cap) list[pos] = val;
        }
    }
    return pos;
}

// ---------------- kernel A: init + masters + ALL weight builds (fused) ----------------
#define S0 NN
#define S1 (KP1 * 128)
#define S2 (256 * 128)
#define S3 (128 * 64)
#define S4 64
#define S5 (KP2 * 128)
#define S6 (KP2 * 64)
#define S7 (KP2 * 256)
#define KA_TOTAL (S0 + S1 + S2 + S3 + S4 + S5 + S6 + S7)

__global__ void kA(const int* __restrict__ batch, int n_graphs,
                   const float* __restrict__ wproj, const float* __restrict__ bproj,
                   const float* __restrict__ ws1, const float* __restrict__ bs1,
                   const float* __restrict__ wmx1, const float* __restrict__ wme1,
                   const float* __restrict__ wes1, const float* __restrict__ wed1,
                   const float* __restrict__ wee1, const float* __restrict__ be1,
                   const float* __restrict__ ws2, const float* __restrict__ bs2,
                   const float* __restrict__ wmx2, const float* __restrict__ wme2,
                   const float* __restrict__ wes2, const float* __restrict__ wed2,
                   const float* __restrict__ wee2, const float* __restrict__ be2,
                   const float* __restrict__ ws3, const float* __restrict__ bs3,
                   const float* __restrict__ wmx3, const float* __restrict__ wme3) {
    int t = blockIdx.x * blockDim.x + threadIdx.x;
    if (t < S0) {
        bool m = (t == 0) || (batch[t] != batch[t - 1]);
        g_needX1[t] = 0;
        g_needX2[t] = m ? 1 : 0;
        g_needX3[t] = m ? 1 : 0;
        g_invX1[t] = -1;
        if (t < ACAP) g_csrCnt[t] = 0;
        if (m) g_outNode[batch[t]] = t;
        if (t < 8) g_cnt[t] = (t == 6) ? n_graphs : 0;
        return;
    }
    t -= S0;
    if (t < S1) {   // W1n [KP1 x 128]
        int k = t >> 7, j = t & 127;
        float v = 0.f;
        if (k < 256) v = ws1[k * 128 + j];
        else if (k < 512) v = wmx1[(k - 256) * 128 + j];
        else if (k < 640) { int p = k - 512; float s = 0.f;
            for (int q = 0; q < 64; q++) s += wproj[p * 64 + q] * wme1[q * 128 + j]; v = s; }
        else if (k == 640) { float s = 0.f;
            for (int q = 0; q < 64; q++) s += bproj[q] * wme1[q * 128 + j]; v = s; }
        else if (k == 641) v = bs1[j];
        g_W1n[t] = v;
        return;
    }
    t -= S1;
    if (t < S2) {   // Wpsd [256 x 128] : cols 0-63 wes1, 64-127 wed1
        int k = t >> 7, j = t & 127;
        g_Wpsd[t] = (j < 64) ? wes1[k * 64 + j] : wed1[k * 64 + (j - 64)];
        return;
    }
    t -= S2;
    if (t < S3) {   // Wq [128 x 64] = wproj @ wee1
        int k = t >> 6, j = t & 63;
        float s = 0.f;
        for (int p = 0; p < 64; p++) s += wproj[k * 64 + p] * wee1[p * 64 + j];
        g_Wq[t] = s;
        return;
    }
    t -= S3;
    if (t < S4) {   // Ce1[64] = bproj @ wee1 + be1
        float s = 0.f;
        for (int p = 0; p < 64; p++) s += bproj[p] * wee1[p * 64 + t];
        g_Ce1[t] = s + be1[t];
        return;
    }
    t -= S4;
    if (t < S5) {   // W2n [KP2 x 128]
        int k = t >> 7, j = t & 127;
        float v = 0.f;
        if (k < 128) v = ws2[k * 128 + j];
        else if (k < 256) v = wmx2[(k - 128) * 128 + j];
        else if (k < 320) v = wme2[(k - 256) * 128 + j];
        else if (k == 320) v = bs2[j];
        g_W2n[t] = v;
        return;
    }
    t -= S5;
    if (t < S6) {   // W2e [KP2 x 64]
        int k = t >> 6, j = t & 63;
        float v = 0.f;
        if (k < 128) v = wes2[k * 64 + j];
        else if (k < 256) v = wed2[(k - 128) * 64 + j];
        else if (k < 320) v = wee2[(k - 256) * 64 + j];
        else if (k == 320) v = be2[j];
        g_W2e[t] = v;
        return;
    }
    t -= S6;
    if (t < S7) {   // W3 [KP2 x 256]
        int k = t >> 8, j = t & 255;
        float v = 0.f;
        if (k < 128) v = ws3[k * 256 + j];
        else if (k < 256) v = wmx3[(k - 128) * 256 + j];
        else if (k < 320) v = wme3[(k - 256) * 256 + j];
        else if (k == 320) v = bs3[j];
        g_W3[t] = v;
    }
}

// ---------------- marking ----------------
__global__ void k_passA(const int* __restrict__ src, const int* __restrict__ dst) {
    int e = blockIdx.x * blockDim.x + threadIdx.x;
    if (e < EE && g_needX3[dst[e]]) g_needX2[src[e]] = 1;
}

__global__ void k_passB(const int* __restrict__ src, const int* __restrict__ dst) {
    int t = blockIdx.x * blockDim.x + threadIdx.x;
    if (t < NN && g_needX2[t]) g_needX1[t] = 1;     // prop (fused)
    if (t < EE) {
        int d = dst[t];
        unsigned char l3 = g_needX3[d];
        unsigned char l2 = g_needX2[d];
        if (l2 | l3) g_needX1[src[t]] = 1;
        if (l3)      g_needX1[d] = 1;
    }
}

__global__ void k_compactN() {
    int i = blockIdx.x * blockDim.x + threadIdx.x;
    int p = warp_push(g_nX1, &g_cnt[4], (i < NN) && g_needX1[i], i, ACAP);
    if (p >= 0 && p < ACAP) g_invX1[i] = p;
    warp_push(g_nX2, &g_cnt[5], (i < NN) && g_needX2[i], i, ACAP);
}

// edge classification lists + CSR histogram + zeroing of layer-2/3 accumulators
__global__ void k_passC(const int* __restrict__ dst) {
    int e = blockIdx.x * blockDim.x + threadIdx.x;   // EE % 256 == 0: full warps
    int d = dst[e];
    unsigned char l3 = g_needX3[d];
    unsigned char l2 = g_needX2[d];
    int p = warp_push(g_eListE1, &g_cnt[1], (l2 | l3) != 0, e, ACAP);
    if (p >= 0) g_e1pos[e] = p;
    warp_push(g_eListL2, &g_cnt[2], l2 != 0, e, ACAP);
    warp_push(g_eListL3, &g_cnt[3], l3 != 0, e, E2CAP);
    int ci = g_invX1[d];
    if (ci >= 0) atomicAdd(&g_csrCnt[ci], 1);

    // zero sx2/se2 rows (nX2) and sx3/se3 rows (masters)
    int stride = gridDim.x * blockDim.x;
    int c2 = g_cnt[5]; if (c2 > ACAP) c2 = ACAP;
    for (int t = e; t < c2 * 192; t += stride) {
        int i = t / 192, c = t - i * 192; int n = g_nX2[i];
        if (c < 128) g_sx2[(size_t)n * 128 + c] = 0.f;
        else         g_se2[(size_t)n * 64 + (c - 128)] = 0.f;
    }
    int cg = g_cnt[6];
    for (int t = e; t < cg * 192; t += stride) {
        int g = t / 192, c = t - g * 192; int n = g_outNode[g];
        if (c < 128) g_sx3[(size_t)n * 128 + c] = 0.f;
        else         g_se3[(size_t)n * 64 + (c - 128)] = 0.f;
    }
}

__global__ void k_scan() {          // single block, 1024 threads
    __shared__ int sh[1024];
    int c1 = g_cnt[4]; if (c1 > ACAP) c1 = ACAP;
    int run = 0;
    for (int base = 0; base < c1; base += 1024) {
        int idx = base + threadIdx.x;
        int v = (idx < c1) ? g_csrCnt[idx] : 0;
        sh[threadIdx.x] = v;
        __syncthreads();
        for (int s = 1; s < 1024; s <<= 1) {
            int t = (threadIdx.x >= s) ? sh[threadIdx.x - s] : 0;
            __syncthreads();
            sh[threadIdx.x] += t;
            __syncthreads();
        }
        if (idx < c1) {
            int excl = run + sh[threadIdx.x] - v;
            g_csrOff[idx] = excl;
            g_csrCur[idx] = excl;
        }
        run += sh[1023];
        __syncthreads();
    }
    if (threadIdx.x == 0) g_csrOff[c1] = run;
}

__global__ void k_fill(const int* __restrict__ dst) {
    int e = blockIdx.x * blockDim.x + threadIdx.x;
    if (e < EE) {
        int ci = g_invX1[dst[e]];
        if (ci >= 0) {
            int p = atomicAdd(&g_csrCur[ci], 1);
            g_csrE[p] = e;
        }
    }
}

// ---------------- layer-1 aggregation: one warp per need1 node, writes A row ----------------
__global__ void k_agg1(const float* __restrict__ x, const float* __restrict__ ea,
                       const int* __restrict__ src) {
    int w = (blockIdx.x * blockDim.x + threadIdx.x) >> 5;
    int lane = threadIdx.x & 31;
    int nw = (gridDim.x * blockDim.x) >> 5;
    int c1 = g_cnt[4]; if (c1 > ACAP) c1 = ACAP;
    for (int i = w; i < c1; i += nw) {
        int n = g_nX1[i];
        int off = g_csrOff[i], end = g_csrOff[i + 1];
        float4 sxa = make_float4(0.f, 0.f, 0.f, 0.f);
        float4 sxb = make_float4(0.f, 0.f, 0.f, 0.f);
        float4 sef = make_float4(0.f, 0.f, 0.f, 0.f);
        for (int j = off; j < end; j++) {
            int e = g_csrE[j];
            int s = src[e];
            const float4* xr = (const float4*)(x + (size_t)s * 256);
            float4 a = xr[lane], b = xr[lane + 32];
            sxa.x += a.x; sxa.y += a.y; sxa.z += a.z; sxa.w += a.w;
            sxb.x += b.x; sxb.y += b.y; sxb.z += b.z; sxb.w += b.w;
            const float4* er = (const float4*)(ea + (size_t)e * 128);
            float4 c = er[lane];
            sef.x += c.x; sef.y += c.y; sef.z += c.z; sef.w += c.w;
        }
        float* A = g_Acat + (size_t)i * KP1;
        const float4* xn = (const float4*)(x + (size_t)n * 256);
        ((float4*)A)[lane]      = xn[lane];
        ((float4*)A)[lane + 32] = xn[lane + 32];
        ((float4*)(A + 256))[lane]      = sxa;
        ((float4*)(A + 256))[lane + 32] = sxb;
        ((float4*)(A + 512))[lane]      = sef;
        if (lane == 0) {
            A[640] = (float)(end - off);
            A[641] = 1.f;
            A[642] = 0.f; A[643] = 0.f; A[644] = 0.f;
            A[645] = 0.f; A[646] = 0.f; A[647] = 0.f;
        }
    }
}

// ---------------- generic tiled GEMM ----------------
// Out[dest?dest[i]:i, :] = act( A[rList?rList[i]:i, 0:KP] @ W )
template <int KP, int N, bool RELU>
__global__ void k_gemm(const float* __restrict__ A, int lda, const int* __restrict__ rList,
                       const float* __restrict__ W, float* __restrict__ Out,
                       const int* __restrict__ dest, int cidx, int cap) {
    constexpr int CN = N / 32;
    __shared__ float sAT[8][64];
    __shared__ float sW[8][N];
    int M = g_cnt[cidx]; if (M > cap) M = cap;
    const int trow = threadIdx.x >> 5, tcol = threadIdx.x & 31;
    for (int mt = blockIdx.x; mt * 64 < M; mt += gridDim.x) {
        const int m0 = mt * 64;
        float acc[8][CN];
        #pragma unroll
        for (int r = 0; r < 8; r++)
            #pragma unroll
            for (int c = 0; c < CN; c++) acc[r][c] = 0.f;

        for (int k0 = 0; k0 < KP; k0 += 8) {
            __syncthreads();
            if (threadIdx.x < 128) {
                int r = threadIdx.x >> 1, kq = (threadIdx.x & 1) * 4;
                int ar = m0 + r;
                float4 v = make_float4(0.f, 0.f, 0.f, 0.f);
                if (ar < M) {
                    int row = rList ? rList[ar] : ar;
                    v = *(const float4*)(A + (size_t)row * lda + k0 + kq);
                }
                sAT[kq + 0][r] = v.x; sAT[kq + 1][r] = v.y;
                sAT[kq + 2][r] = v.z; sAT[kq + 3][r] = v.w;
            }
            #pragma unroll 2
            for (int i = threadIdx.x; i < 2 * N; i += 256) {
                int kk = i / (N / 4), c4 = i - kk * (N / 4);
                *(float4*)&sW[kk][c4 * 4] = *(const float4*)(W + (size_t)(k0 + kk) * N + c4 * 4);
            }
            __syncthreads();
            #pragma unroll
            for (int kk = 0; kk < 8; kk++) {
                float a[8];
                *(float4*)&a[0] = *(const float4*)&sAT[kk][trow * 8];
                *(float4*)&a[4] = *(const float4*)&sAT[kk][trow * 8 + 4];
                float b[CN];
                if constexpr (CN == 2) {
                    float2 bv = *(const float2*)&sW[kk][tcol * 2];
                    b[0] = bv.x; b[1] = bv.y;
                } else {
                    #pragma unroll
                    for (int g = 0; g < CN / 4; g++) {
                        float4 bv = *(const float4*)&sW[kk][g * 128 + tcol * 4];
                        b[g * 4 + 0] = bv.x; b[g * 4 + 1] = bv.y;
                        b[g * 4 + 2] = bv.z; b[g * 4 + 3] = bv.w;
                    }
                }
                #pragma unroll
                for (int r = 0; r < 8; r++)
                    #pragma unroll
                    for (int c = 0; c < CN; c++)
                        acc[r][c] = fmaf(a[r], b[c], acc[r][c]);
            }
        }
        #pragma unroll
        for (int r = 0; r < 8; r++) {
            int row = m0 + trow * 8 + r;
            if (row < M) {
                int drow = dest ? dest[row] : row;
                float* o = Out + (size_t)drow * N;
                if constexpr (CN == 2) {
                    float2 v;
                    v.x = RELU ? fmaxf(acc[r][0], 0.f) : acc[r][0];
                    v.y = RELU ? fmaxf(acc[r][1], 0.f) : acc[r][1];
                    *(float2*)(o + tcol * 2) = v;
                } else {
                    #pragma unroll
                    for (int g = 0; g < CN / 4; g++) {
                        float4 v;
                        v.x = RELU ? fmaxf(acc[r][g * 4 + 0], 0.f) : acc[r][g * 4 + 0];
                        v.y = RELU ? fmaxf(acc[r][g * 4 + 1], 0.f) : acc[r][g * 4 + 1];
                        v.z = RELU ? fmaxf(acc[r][g * 4 + 2], 0.f) : acc[r][g * 4 + 2];
                        v.w = RELU ? fmaxf(acc[r][g * 4 + 3], 0.f) : acc[r][g * 4 + 3];
                        *(float4*)(o + g * 128 + tcol * 4) = v;
                    }
                }
            }
        }
        __syncthreads();
    }
}

// ---------------- e1 combine: e1r = relu(ps[s] + pd[d] + q + c) ----------------
__global__ void k_combine1(const int* __restrict__ src, const int* __restrict__ dst) {
    int cnt = g_cnt[1]; if (cnt > ACAP) cnt = ACAP;
    int tot = cnt * 64;
    int stride = gridDim.x * blockDim.x;
    for (int t = blockIdx.x * blockDim.x + threadIdx.x; t < tot; t += stride) {
        int idx = t >> 6, c = t & 63;
        int e = g_eListE1[idx];
        int s = src[e], d = dst[e];
        float v = g_psd[(size_t)s * 128 + c] + g_psd[(size_t)d * 128 + 64 + c]
                + g_q[(size_t)idx * 64 + c] + g_Ce1[c];
        g_e1r[(size_t)idx * 64 + c] = fmaxf(v, 0.f);
    }
}

// ---------------- layer-2/3 scatters (small, atomics fine) ----------------
__global__ void k_scatter2(const int* __restrict__ src, const int* __restrict__ dst) {
    int warpId = (blockIdx.x * blockDim.x + threadIdx.x) >> 5;
    int lane = threadIdx.x & 31;
    int nw = (gridDim.x * blockDim.x) >> 5;
    int cnt = g_cnt[2]; if (cnt > ACAP) cnt = ACAP;
    for (int idx = warpId; idx < cnt; idx += nw) {
        int e = g_eListL2[idx];
        int s = src[e], d = dst[e];
        int ep = g_e1pos[e];
        #pragma unroll
        for (int c = 0; c < 4; c++)
            atomicAdd(&g_sx2[(size_t)d * 128 + lane + 32 * c], g_x1r[(size_t)s * 128 + lane + 32 * c]);
        #pragma unroll
        for (int c = 0; c < 2; c++)
            atomicAdd(&g_se2[(size_t)d * 64 + lane + 32 * c], g_e1r[(size_t)ep * 64 + lane + 32 * c]);
    }
}

__global__ void k_scatter3(const int* __restrict__ src, const int* __restrict__ dst) {
    int warpId = (blockIdx.x * blockDim.x + threadIdx.x) >> 5;
    int lane = threadIdx.x & 31;
    int nw = (gridDim.x * blockDim.x) >> 5;
    int cnt = g_cnt[3]; if (cnt > E2CAP) cnt = E2CAP;
    for (int idx = warpId; idx < cnt; idx += nw) {
        int e = g_eListL3[idx];
        int s = src[e], d = dst[e];
        #pragma unroll
        for (int c = 0; c < 4; c++)
            atomicAdd(&g_sx3[(size_t)d * 128 + lane + 32 * c], g_x2r[(size_t)s * 128 + lane + 32 * c]);
        #pragma unroll
        for (int c = 0; c < 2; c++)
            atomicAdd(&g_se3[(size_t)d * 64 + lane + 32 * c], g_e2r[(size_t)idx * 64 + lane + 32 * c]);
    }
}

// ---------------- layer-2/3 A-matrix gathers ----------------
__global__ void k_gatherN2() {
    int cnt = g_cnt[5]; if (cnt > ACAP) cnt = ACAP;
    for (int i = blockIdx.x; i < cnt; i += gridDim.x) {
        int n = g_nX2[i];
        float* A = g_Acat + (size_t)i * KP2;
        for (int k = threadIdx.x; k < KP2; k += blockDim.x) {
            float v;
            if (k < 128) v = g_x1r[(size_t)n * 128 + k];
            else if (k < 256) v = g_sx2[(size_t)n * 128 + (k - 128)];
            else if (k < 320) v = g_se2[(size_t)n * 64 + (k - 256)];
            else if (k == 320) v = 1.f;
            else v = 0.f;
            A[k] = v;
        }
    }
}

__global__ void k_gatherE2(const int* __restrict__ src, const int* __restrict__ dst) {
    int cnt = g_cnt[3]; if (cnt > E2CAP) cnt = E2CAP;
    for (int i = blockIdx.x; i < cnt; i += gridDim.x) {
        int e = g_eListL3[i];
        int s = src[e], d = dst[e];
        int ep = g_e1pos[e];
        float* A = g_Acat + (size_t)i * KP2;
        for (int k = threadIdx.x; k < KP2; k += blockDim.x) {
            float v;
            if (k < 128) v = g_x1r[(size_t)s * 128 + k];
            else if (k < 256) v = g_x1r[(size_t)d * 128 + (k - 128)];
            else if (k < 320) v = g_e1r[(size_t)ep * 64 + (k - 256)];
            else if (k == 320) v = 1.f;
            else v = 0.f;
            A[k] = v;
        }
    }
}

__global__ void k_gatherF() {
    int cnt = g_cnt[6];
    for (int g = blockIdx.x; g < cnt; g += gridDim.x) {
        int n = g_outNode[g];
        float* A = g_Acat + (size_t)g * KP2;
        for (int k = threadIdx.x; k < KP2; k += blockDim.x) {
            float v;
            if (k < 128) v = g_x2r[(size_t)n * 128 + k];
            else if (k < 256) v = g_sx3[(size_t)n * 128 + (k - 128)];
            else if (k < 320) v = g_se3[(size_t)n * 64 + (k - 256)];
            else if (k == 320) v = 1.f;
            else v = 0.f;
            A[k] = v;
        }
    }
}

// ---------------- host ----------------
extern "C" void kernel_launch(void* const* d_in, const int* in_sizes, int n_in,
                              void* d_out, int out_size) {
    const float* x     = (const float*)d_in[0];
    const int*   ei    = (const int*)d_in[1];
    const int*   src   = ei;
    const int*   dst   = ei + EE;
    const float* ea    = (const float*)d_in[2];
    const int*   batch = (const int*)d_in[3];
    const float* wproj = (const float*)d_in[4];
    const float* bproj = (const float*)d_in[5];
    const float* ws1 = (const float*)d_in[6],  *bs1 = (const float*)d_in[7];
    const float* wmx1 = (const float*)d_in[8], *wme1 = (const float*)d_in[9];
    const float* wes1 = (const float*)d_in[10], *wed1 = (const float*)d_in[11];
    const float* wee1 = (const float*)d_in[12], *be1 = (const float*)d_in[13];
    const float* ws2 = (const float*)d_in[14], *bs2 = (const float*)d_in[15];
    const float* wmx2 = (const float*)d_in[16], *wme2 = (const float*)d_in[17];
    const float* wes2 = (const float*)d_in[18], *wed2 = (const float*)d_in[19];
    const float* wee2 = (const float*)d_in[20], *be2 = (const float*)d_in[21];
    const float* ws3 = (const float*)d_in[22], *bs3 = (const float*)d_in[23];
    const float* wmx3 = (const float*)d_in[24], *wme3 = (const float*)d_in[25];
    float* out = (float*)d_out;
    int n_graphs = out_size / 256;

    float *Acat, *W1n, *Wpsd, *Wq, *W2n, *W2e, *W3;
    float *x1r, *psd, *q, *e1r, *x2r, *e2r;
    int *nX1, *nX2, *eE1;
    cudaGetSymbolAddress((void**)&Acat, g_Acat);
    cudaGetSymbolAddress((void**)&W1n,  g_W1n);
    cudaGetSymbolAddress((void**)&Wpsd, g_Wpsd);
    cudaGetSymbolAddress((void**)&Wq,   g_Wq);
    cudaGetSymbolAddress((void**)&W2n,  g_W2n);
    cudaGetSymbolAddress((void**)&W2e,  g_W2e);
    cudaGetSymbolAddress((void**)&W3,   g_W3);
    cudaGetSymbolAddress((void**)&x1r,  g_x1r);
    cudaGetSymbolAddress((void**)&psd,  g_psd);
    cudaGetSymbolAddress((void**)&q,    g_q);
    cudaGetSymbolAddress((void**)&e1r,  g_e1r);
    cudaGetSymbolAddress((void**)&x2r,  g_x2r);
    cudaGetSymbolAddress((void**)&e2r,  g_e2r);
    cudaGetSymbolAddress((void**)&nX1,  g_nX1);
    cudaGetSymbolAddress((void**)&nX2,  g_nX2);
    cudaGetSymbolAddress((void**)&eE1,  g_eListE1);

    const int NB_N = (NN + 255) / 256;
    const int NB_E = EE / 256;
    const int NB_A = (KA_TOTAL + 255) / 256;

    // setup + weights (1 launch)
    kA<<<NB_A, 256>>>(batch, n_graphs, wproj, bproj,
                      ws1, bs1, wmx1, wme1, wes1, wed1, wee1, be1,
                      ws2, bs2, wmx2, wme2, wes2, wed2, wee2, be2,
                      ws3, bs3, wmx3, wme3);
    // marking / compaction / CSR
    k_passA<<<NB_E, 256>>>(src, dst);
    k_passB<<<NB_E, 256>>>(src, dst);
    k_compactN<<<NB_N, 256>>>();
    k_passC<<<NB_E, 256>>>(dst);
    k_scan<<<1, 1024>>>();
    k_fill<<<NB_E, 256>>>(dst);

    // layer 1
    k_agg1<<<2048, 256>>>(x, ea, src);
    k_gemm<KP1, 128, true ><<<224, 256>>>(Acat, KP1, (const int*)0, W1n,  x1r, nX1, 4, ACAP);
    k_gemm<256, 128, false><<<224, 256>>>(Acat, KP1, (const int*)0, Wpsd, psd, nX1, 4, ACAP);
    k_gemm<128,  64, false><<<224, 256>>>(ea,   128, eE1,           Wq,   q,   (const int*)0, 1, ACAP);
    k_combine1<<<512, 256>>>(src, dst);

    // layer 2
    k_scatter2<<<256, 256>>>(src, dst);
    k_gatherN2<<<256, 256>>>();
    k_gemm<KP2, 128, true><<<16, 256>>>(Acat, KP2, (const int*)0, W2n, x2r, nX2, 5, ACAP);
    k_gatherE2<<<256, 256>>>(src, dst);
    k_gemm<KP2, 64, true><<<16, 256>>>(Acat, KP2, (const int*)0, W2e, e2r, (const int*)0, 3, E2CAP);

    // layer 3 + output
    k_scatter3<<<64, 256>>>(src, dst);
    k_gatherF<<<64, 256>>>();
    k_gemm<KP2, 256, false><<<1, 256>>>(Acat, KP2, (const int*)0, W3, out, (const int*)0, 6, NGMAX);
}

// round 7
// speedup vs baseline: 1.4951x; 1.0131x over previous
#include <cuda_runtime.h>

#define NN    50000
#define EE    800000
#define NGMAX 64
#define KP1   648     // 256(x) + 256(sum x_src) + 128(sum ea) + deg + 1 + pad
#define KP2   328     // 128 + 128 + 64 + 1 + pad
#define ACAP  24000
#define E2CAP 4000

// ---------------- device scratch ----------------
__device__ unsigned char g_needX1[NN], g_needX2[NN], g_needX3[NN];
__device__ int g_cnt[8];   // 1:E1e 2:L2e 3:L3e 4:X1n 5:X2n 6:ngraphs
__device__ int g_eListE1[ACAP], g_eListL2[ACAP], g_eListL3[E2CAP];
__device__ int g_e1pos[EE];
__device__ int g_nX1[ACAP], g_nX2[ACAP], g_outNode[NGMAX], g_invX1[NN];
__device__ int g_csrCnt[ACAP], g_csrOff[ACAP + 1], g_csrCur[ACAP];
__device__ int g_csrE[EE];

__device__ float g_Acat[(size_t)ACAP * KP1];
__device__ float g_x1r[(size_t)NN * 128];
__device__ float g_psd[(size_t)NN * 128];          // [es(64) | ed(64)] per node
__device__ float g_e1r[(size_t)ACAP * 64];
__device__ float g_sx2[(size_t)NN * 128], g_se2[(size_t)NN * 64];
__device__ float g_x2r[(size_t)NN * 128];
__device__ float g_e2r[(size_t)E2CAP * 64];
__device__ float g_sx3[(size_t)NN * 128], g_se3[(size_t)NN * 64];

__device__ float g_W1n[KP1 * 128];
__device__ float g_Wpsd[256 * 128];
__device__ float g_Wq[128 * 64];
__device__ float g_Ce1[64];
__device__ float g_W2n[KP2 * 128], g_W2e[KP2 * 64], g_W3[KP2 * 256];

// ---------------- helpers ----------------
__device__ __forceinline__ int warp_push(int* list, int* cnt, bool flag, int val, int cap) {
    unsigned bal = __ballot_sync(0xffffffffu, flag);
    int pos = -1;
    if (bal) {
        int lane = threadIdx.x & 31;
        int leader = __ffs(bal) - 1;
        int base = 0;
        if (lane == leader) base = atomicAdd(cnt, __popc(bal));
        base = __shfl_sync(0xffffffffu, base, leader);
        if (flag) {
            pos = base + __popc(bal & ((1u << lane) - 1u));
            if (pos < cap) list[pos] = val;
        }
    }
    return pos;
}

// ---------------- kernel A: init + masters + ALL weight builds (fused) ----------------
#define S0 NN
#define S1 (KP1 * 128)
#define S2 (256 * 128)
#define S3 (128 * 64)
#define S4 64
#define S5 (KP2 * 128)
#define S6 (KP2 * 64)
#define S7 (KP2 * 256)
#define KA_TOTAL (S0 + S1 + S2 + S3 + S4 + S5 + S6 + S7)

__global__ void kA(const int* __restrict__ batch, int n_graphs,
                   const float* __restrict__ wproj, const float* __restrict__ bproj,
                   const float* __restrict__ ws1, const float* __restrict__ bs1,
                   const float* __restrict__ wmx1, const float* __restrict__ wme1,
                   const float* __restrict__ wes1, const float* __restrict__ wed1,
                   const float* __restrict__ wee1, const float* __restrict__ be1,
                   const float* __restrict__ ws2, const float* __restrict__ bs2,
                   const float* __restrict__ wmx2, const float* __restrict__ wme2,
                   const float* __restrict__ wes2, const float* __restrict__ wed2,
                   const float* __restrict__ wee2, const float* __restrict__ be2,
                   const float* __restrict__ ws3, const float* __restrict__ bs3,
                   const float* __restrict__ wmx3, const float* __restrict__ wme3) {
    int t = blockIdx.x * blockDim.x + threadIdx.x;
    if (t < S0) {
        bool m = (t == 0) || (batch[t] != batch[t - 1]);
        g_needX1[t] = 0;
        g_needX2[t] = m ? 1 : 0;
        g_needX3[t] = m ? 1 : 0;
        g_invX1[t] = -1;
        if (t < ACAP) g_csrCnt[t] = 0;
        if (m) g_outNode[batch[t]] = t;
        if (t < 8) g_cnt[t] = (t == 6) ? n_graphs : 0;
        return;
    }
    t -= S0;
    if (t < S1) {   // W1n [KP1 x 128]
        int k = t >> 7, j = t & 127;
        float v = 0.f;
        if (k < 256) v = ws1[k * 128 + j];
        else if (k < 512) v = wmx1[(k - 256) * 128 + j];
        else if (k < 640) { int p = k - 512; float s = 0.f;
            for (int q = 0; q < 64; q++) s += wproj[p * 64 + q] * wme1[q * 128 + j]; v = s; }
        else if (k == 640) { float s = 0.f;
            for (int q = 0; q < 64; q++) s += bproj[q] * wme1[q * 128 + j]; v = s; }
        else if (k == 641) v = bs1[j];
        g_W1n[t] = v;
        return;
    }
    t -= S1;
    if (t < S2) {   // Wpsd [256 x 128] : cols 0-63 wes1, 64-127 wed1
        int k = t >> 7, j = t & 127;
        g_Wpsd[t] = (j < 64) ? wes1[k * 64 + j] : wed1[k * 64 + (j - 64)];
        return;
    }
    t -= S2;
    if (t < S3) {   // Wq [128 x 64] = wproj @ wee1
        int k = t >> 6, j = t & 63;
        float s = 0.f;
        for (int p = 0; p < 64; p++) s += wproj[k * 64 + p] * wee1[p * 64 + j];
        g_Wq[t] = s;
        return;
    }
    t -= S3;
    if (t < S4) {   // Ce1[64] = bproj @ wee1 + be1
        float s = 0.f;
        for (int p = 0; p < 64; p++) s += bproj[p] * wee1[p * 64 + t];
        g_Ce1[t] = s + be1[t];
        return;
    }
    t -= S4;
    if (t < S5) {   // W2n [KP2 x 128]
        int k = t >> 7, j = t & 127;
        float v = 0.f;
        if (k < 128) v = ws2[k * 128 + j];
        else if (k < 256) v = wmx2[(k - 128) * 128 + j];
        else if (k < 320) v = wme2[(k - 256) * 128 + j];
        else if (k == 320) v = bs2[j];
        g_W2n[t] = v;
        return;
    }
    t -= S5;
    if (t < S6) {   // W2e [KP2 x 64]
        int k = t >> 6, j = t & 63;
        float v = 0.f;
        if (k < 128) v = wes2[k * 64 + j];
        else if (k < 256) v = wed2[(k - 128) * 64 + j];
        else if (k < 320) v = wee2[(k - 256) * 64 + j];
        else if (k == 320) v = be2[j];
        g_W2e[t] = v;
        return;
    }
    t -= S6;
    if (t < S7) {   // W3 [KP2 x 256]
        int k = t >> 8, j = t & 255;
        float v = 0.f;
        if (k < 128) v = ws3[k * 256 + j];
        else if (k < 256) v = wmx3[(k - 128) * 256 + j];
        else if (k < 320) v = wme3[(k - 256) * 256 + j];
        else if (k == 320) v = bs3[j];
        g_W3[t] = v;
    }
}

// ---------------- marking ----------------
__global__ void k_passA(const int* __restrict__ src, const int* __restrict__ dst) {
    int e = blockIdx.x * blockDim.x + threadIdx.x;
    if (e < EE && g_needX3[dst[e]]) g_needX2[src[e]] = 1;
}

__global__ void k_passB(const int* __restrict__ src, const int* __restrict__ dst) {
    int t = blockIdx.x * blockDim.x + threadIdx.x;
    if (t < NN && g_needX2[t]) g_needX1[t] = 1;     // prop (fused)
    if (t < EE) {
        int d = dst[t];
        unsigned char l3 = g_needX3[d];
        unsigned char l2 = g_needX2[d];
        if (l2 | l3) g_needX1[src[t]] = 1;
        if (l3)      g_needX1[d] = 1;
    }
}

__global__ void k_compactN() {
    int i = blockIdx.x * blockDim.x + threadIdx.x;
    int p = warp_push(g_nX1, &g_cnt[4], (i < NN) && g_needX1[i], i, ACAP);
    if (p >= 0 && p < ACAP) g_invX1[i] = p;
    warp_push(g_nX2, &g_cnt[5], (i < NN) && g_needX2[i], i, ACAP);
}

// edge lists + CSR histogram + zeroing of layer-2/3 accumulators
__global__ void k_passC(const int* __restrict__ dst) {
    int e = blockIdx.x * blockDim.x + threadIdx.x;   // EE % 256 == 0: full warps
    int d = dst[e];
    unsigned char l3 = g_needX3[d];
    unsigned char l2 = g_needX2[d];
    int p = warp_push(g_eListE1, &g_cnt[1], (l2 | l3) != 0, e, ACAP);
    if (p >= 0) g_e1pos[e] = p;
    warp_push(g_eListL2, &g_cnt[2], l2 != 0, e, ACAP);
    warp_push(g_eListL3, &g_cnt[3], l3 != 0, e, E2CAP);
    int ci = g_invX1[d];
    if (ci >= 0) atomicAdd(&g_csrCnt[ci], 1);

    int stride = gridDim.x * blockDim.x;
    int c2 = g_cnt[5]; if (c2 > ACAP) c2 = ACAP;
    for (int t = e; t < c2 * 192; t += stride) {
        int i = t / 192, c = t - i * 192; int n = g_nX2[i];
        if (c < 128) g_sx2[(size_t)n * 128 + c] = 0.f;
        else         g_se2[(size_t)n * 64 + (c - 128)] = 0.f;
    }
    int cg = g_cnt[6];
    for (int t = e; t < cg * 192; t += stride) {
        int g = t / 192, c = t - g * 192; int n = g_outNode[g];
        if (c < 128) g_sx3[(size_t)n * 128 + c] = 0.f;
        else         g_se3[(size_t)n * 64 + (c - 128)] = 0.f;
    }
}

__global__ void k_scan() {          // single block, 1024 threads
    __shared__ int sh[1024];
    int c1 = g_cnt[4]; if (c1 > ACAP) c1 = ACAP;
    int run = 0;
    for (int base = 0; base < c1; base += 1024) {
        int idx = base + threadIdx.x;
        int v = (idx < c1) ? g_csrCnt[idx] : 0;
        sh[threadIdx.x] = v;
        __syncthreads();
        for (int s = 1; s < 1024; s <<= 1) {
            int t = (threadIdx.x >= s) ? sh[threadIdx.x - s] : 0;
            __syncthreads();
            sh[threadIdx.x] += t;
            __syncthreads();
        }
        if (idx < c1) {
            int excl = run + sh[threadIdx.x] - v;
            g_csrOff[idx] = excl;
            g_csrCur[idx] = excl;
        }
        run += sh[1023];
        __syncthreads();
    }
    if (threadIdx.x == 0) g_csrOff[c1] = run;
}

__global__ void k_fill(const int* __restrict__ dst) {
    int e = blockIdx.x * blockDim.x + threadIdx.x;
    if (e < EE) {
        int ci = g_invX1[dst[e]];
        if (ci >= 0) {
            int p = atomicAdd(&g_csrCur[ci], 1);
            g_csrE[p] = e;
        }
    }
}

// ---------------- layer-1 aggregation: one warp per need1 node ----------------
__global__ void k_agg1(const float* __restrict__ x, const float* __restrict__ ea,
                       const int* __restrict__ src) {
    int w = (blockIdx.x * blockDim.x + threadIdx.x) >> 5;
    int lane = threadIdx.x & 31;
    int nw = (gridDim.x * blockDim.x) >> 5;
    int c1 = g_cnt[4]; if (c1 > ACAP) c1 = ACAP;
    for (int i = w; i < c1; i += nw) {
        int n = g_nX1[i];
        int off = g_csrOff[i], end = g_csrOff[i + 1];
        float4 sxa = make_float4(0.f, 0.f, 0.f, 0.f);
        float4 sxb = make_float4(0.f, 0.f, 0.f, 0.f);
        float4 sef = make_float4(0.f, 0.f, 0.f, 0.f);
        int j = off;
        for (; j + 2 <= end; j += 2) {       // unroll-2 for MLP
            int e0 = g_csrE[j], e1 = g_csrE[j + 1];
            int s0 = src[e0], s1 = src[e1];
            const float4* x0 = (const float4*)(x + (size_t)s0 * 256);
            const float4* x1 = (const float4*)(x + (size_t)s1 * 256);
            const float4* e0r = (const float4*)(ea + (size_t)e0 * 128);
            const float4* e1r4 = (const float4*)(ea + (size_t)e1 * 128);
            float4 a0 = x0[lane], a1 = x1[lane];
            float4 b0 = x0[lane + 32], b1 = x1[lane + 32];
            float4 c0 = e0r[lane], c1v = e1r4[lane];
            sxa.x += a0.x + a1.x; sxa.y += a0.y + a1.y; sxa.z += a0.z + a1.z; sxa.w += a0.w + a1.w;
            sxb.x += b0.x + b1.x; sxb.y += b0.y + b1.y; sxb.z += b0.z + b1.z; sxb.w += b0.w + b1.w;
            sef.x += c0.x + c1v.x; sef.y += c0.y + c1v.y; sef.z += c0.z + c1v.z; sef.w += c0.w + c1v.w;
        }
        if (j < end) {
            int e = g_csrE[j];
            int s = src[e];
            const float4* xr = (const float4*)(x + (size_t)s * 256);
            float4 a = xr[lane], b = xr[lane + 32];
            sxa.x += a.x; sxa.y += a.y; sxa.z += a.z; sxa.w += a.w;
            sxb.x += b.x; sxb.y += b.y; sxb.z += b.z; sxb.w += b.w;
            const float4* er = (const float4*)(ea + (size_t)e * 128);
            float4 c = er[lane];
            sef.x += c.x; sef.y += c.y; sef.z += c.z; sef.w += c.w;
        }
        float* A = g_Acat + (size_t)i * KP1;
        const float4* xn = (const float4*)(x + (size_t)n * 256);
        ((float4*)A)[lane]      = xn[lane];
        ((float4*)A)[lane + 32] = xn[lane + 32];
        ((float4*)(A + 256))[lane]      = sxa;
        ((float4*)(A + 256))[lane + 32] = sxb;
        ((float4*)(A + 512))[lane]      = sef;
        if (lane == 0) {
            A[640] = (float)(end - off);
            A[641] = 1.f;
            A[642] = 0.f; A[643] = 0.f; A[644] = 0.f;
            A[645] = 0.f; A[646] = 0.f; A[647] = 0.f;
        }
    }
}

// ---------------- A-source fetchers for fused GEMMs ----------------
// AMODE: 0 = dense A (optional rList indirection), 1 = layer2-node, 2 = layer3-edge, 3 = final
template <int AMODE>
__device__ __forceinline__ float4 fetchA(const float* __restrict__ A, int lda,
                                         const int* __restrict__ rList, int r, int k,
                                         const int* __restrict__ src, const int* __restrict__ dst) {
    if constexpr (AMODE == 0) {
        int row = rList ? rList[r] : r;
        return *(const float4*)(A + (size_t)row * lda + k);
    } else if constexpr (AMODE == 1) {
        int n = g_nX2[r];
        if (k < 128) return *(const float4*)(g_x1r + (size_t)n * 128 + k);
        if (k < 256) return *(const float4*)(g_sx2 + (size_t)n * 128 + (k - 128));
        if (k < 320) return *(const float4*)(g_se2 + (size_t)n * 64 + (k - 256));
        return make_float4(k == 320 ? 1.f : 0.f, 0.f, 0.f, 0.f);
    } else if constexpr (AMODE == 2) {
        int e = g_eListL3[r];
        int s = src[e], d = dst[e], ep = g_e1pos[e];
        if (k < 128) return *(const float4*)(g_x1r + (size_t)s * 128 + k);
        if (k < 256) return *(const float4*)(g_x1r + (size_t)d * 128 + (k - 128));
        if (k < 320) return *(const float4*)(g_e1r + (size_t)ep * 64 + (k - 256));
        return make_float4(k == 320 ? 1.f : 0.f, 0.f, 0.f, 0.f);
    } else {
        int n = g_outNode[r];
        if (k < 128) return *(const float4*)(g_x2r + (size_t)n * 128 + k);
        if (k < 256) return *(const float4*)(g_sx3 + (size_t)n * 128 + (k - 128));
        if (k < 320) return *(const float4*)(g_se3 + (size_t)n * 64 + (k - 256));
        return make_float4(k == 320 ? 1.f : 0.f, 0.f, 0.f, 0.f);
    }
}

// ---------------- tiled GEMM (scalar FFMA, proven path) ----------------
// Out[dest?dest[i]:i, :] = act( A[i, 0:KP] @ W ),  optional e1-combine epilogue
template <int KP, int N, bool RELU, int AMODE, bool EPI_E1>
__global__ void __launch_bounds__(256)
k_gemm(const float* __restrict__ A, int lda, const int* __restrict__ rList,
       const float* __restrict__ W, float* __restrict__ Out,
       const int* __restrict__ dest, int cidx, int cap,
       const int* __restrict__ src, const int* __restrict__ dst) {
    constexpr int CN = N / 32;
    __shared__ float sAT[8][64];
    __shared__ float sW[8][N];
    int M = g_cnt[cidx]; if (M > cap) M = cap;
    const int trow = threadIdx.x >> 5, tcol = threadIdx.x & 31;
    for (int mt = blockIdx.x; mt * 64 < M; mt += gridDim.x) {
        const int m0 = mt * 64;
        float acc[8][CN];
        #pragma unroll
        for (int r = 0; r < 8; r++)
            #pragma unroll
            for (int c = 0; c < CN; c++) acc[r][c] = 0.f;

        for (int k0 = 0; k0 < KP; k0 += 8) {
            __syncthreads();
            if (threadIdx.x < 128) {
                int r = threadIdx.x >> 1, kq = (threadIdx.x & 1) * 4;
                int ar = m0 + r;
                float4 v = make_float4(0.f, 0.f, 0.f, 0.f);
                if (ar < M) v = fetchA<AMODE>(A, lda, rList, ar, k0 + kq, src, dst);
                sAT[kq + 0][r] = v.x; sAT[kq + 1][r] = v.y;
                sAT[kq + 2][r] = v.z; sAT[kq + 3][r] = v.w;
            }
            #pragma unroll 2
            for (int i = threadIdx.x; i < 2 * N; i += 256) {
                int kk = i / (N / 4), c4 = i - kk * (N / 4);
                *(float4*)&sW[kk][c4 * 4] = *(const float4*)(W + (size_t)(k0 + kk) * N + c4 * 4);
            }
            __syncthreads();
            #pragma unroll
            for (int kk = 0; kk < 8; kk++) {
                float a[8];
                *(float4*)&a[0] = *(const float4*)&sAT[kk][trow * 8];
                *(float4*)&a[4] = *(const float4*)&sAT[kk][trow * 8 + 4];
                float b[CN];
                if constexpr (CN == 2) {
                    float2 bv = *(const float2*)&sW[kk][tcol * 2];
                    b[0] = bv.x; b[1] = bv.y;
                } else {
                    #pragma unroll
                    for (int g = 0; g < CN / 4; g++) {
                        float4 bv = *(const float4*)&sW[kk][g * 128 + tcol * 4];
                        b[g * 4 + 0] = bv.x; b[g * 4 + 1] = bv.y;
                        b[g * 4 + 2] = bv.z; b[g * 4 + 3] = bv.w;
                    }
                }
                #pragma unroll
                for (int r = 0; r < 8; r++)
                    #pragma unroll
                    for (int c = 0; c < CN; c++)
                        acc[r][c] = fmaf(a[r], b[c], acc[r][c]);
            }
        }
        // epilogue
        #pragma unroll
        for (int r = 0; r < 8; r++) {
            int row = m0 + trow * 8 + r;
            if (row >= M) continue;
            if constexpr (EPI_E1) {
                // e1r[row*64 + col] = relu(q + ps[s] + pd[d] + Ce1), cols tcol*2..+1
                int e = g_eListE1[row];
                int s = src[e], d = dst[e];
                float2 p1 = *(const float2*)&g_psd[(size_t)s * 128 + tcol * 2];
                float2 p2 = *(const float2*)&g_psd[(size_t)d * 128 + 64 + tcol * 2];
                float2 ce = *(const float2*)&g_Ce1[tcol * 2];
                float2 v;
                v.x = fmaxf(acc[r][0] + p1.x + p2.x + ce.x, 0.f);
                v.y = fmaxf(acc[r][1] + p1.y + p2.y + ce.y, 0.f);
                *(float2*)(Out + (size_t)row * 64 + tcol * 2) = v;
            } else {
                int drow = dest ? dest[row] : row;
                float* o = Out + (size_t)drow * N;
                if constexpr (CN == 2) {
                    float2 v;
                    v.x = RELU ? fmaxf(acc[r][0], 0.f) : acc[r][0];
                    v.y = RELU ? fmaxf(acc[r][1], 0.f) : acc[r][1];
                    *(float2*)(o + tcol * 2) = v;
                } else {
                    #pragma unroll
                    for (int g = 0; g < CN / 4; g++) {
                        float4 v;
                        v.x = RELU ? fmaxf(acc[r][g * 4 + 0], 0.f) : acc[r][g * 4 + 0];
                        v.y = RELU ? fmaxf(acc[r][g * 4 + 1], 0.f) : acc[r][g * 4 + 1];
                        v.z = RELU ? fmaxf(acc[r][g * 4 + 2], 0.f) : acc[r][g * 4 + 2];
                        v.w = RELU ? fmaxf(acc[r][g * 4 + 3], 0.f) : acc[r][g * 4 + 3];
                        *(float4*)(o + g * 128 + tcol * 4) = v;
                    }
                }
            }
        }
        __syncthreads();
    }
}

// ---------------- layer-2/3 scatters ----------------
__global__ void k_scatter2(const int* __restrict__ src, const int* __restrict__ dst) {
    int warpId = (blockIdx.x * blockDim.x + threadIdx.x) >> 5;
    int lane = threadIdx.x & 31;
    int nw = (gridDim.x * blockDim.x) >> 5;
    int cnt = g_cnt[2]; if (cnt > ACAP) cnt = ACAP;
    for (int idx = warpId; idx < cnt; idx += nw) {
        int e = g_eListL2[idx];
        int s = src[e], d = dst[e];
        int ep = g_e1pos[e];
        #pragma unroll
        for (int c = 0; c < 4; c++)
            atomicAdd(&g_sx2[(size_t)d * 128 + lane + 32 * c], g_x1r[(size_t)s * 128 + lane + 32 * c]);
        #pragma unroll
        for (int c = 0; c < 2; c++)
            atomicAdd(&g_se2[(size_t)d * 64 + lane + 32 * c], g_e1r[(size_t)ep * 64 + lane + 32 * c]);
    }
}

__global__ void k_scatter3(const int* __restrict__ src, const int* __restrict__ dst) {
    int warpId = (blockIdx.x * blockDim.x + threadIdx.x) >> 5;
    int lane = threadIdx.x & 31;
    int nw = (gridDim.x * blockDim.x) >> 5;
    int cnt = g_cnt[3]; if (cnt > E2CAP) cnt = E2CAP;
    for (int idx = warpId; idx < cnt; idx += nw) {
        int e = g_eListL3[idx];
        int s = src[e], d = dst[e];
        #pragma unroll
        for (int c = 0; c < 4; c++)
            atomicAdd(&g_sx3[(size_t)d * 128 + lane + 32 * c], g_x2r[(size_t)s * 128 + lane + 32 * c]);
        #pragma unroll
        for (int c = 0; c < 2; c++)
            atomicAdd(&g_se3[(size_t)d * 64 + lane + 32 * c], g_e2r[(size_t)idx * 64 + lane + 32 * c]);
    }
}

// ---------------- host ----------------
extern "C" void kernel_launch(void* const* d_in, const int* in_sizes, int n_in,
                              void* d_out, int out_size) {
    const float* x     = (const float*)d_in[0];
    const int*   ei    = (const int*)d_in[1];
    const int*   src   = ei;
    const int*   dst   = ei + EE;
    const float* ea    = (const float*)d_in[2];
    const int*   batch = (const int*)d_in[3];
    const float* wproj = (const float*)d_in[4];
    const float* bproj = (const float*)d_in[5];
    const float* ws1 = (const float*)d_in[6],  *bs1 = (const float*)d_in[7];
    const float* wmx1 = (const float*)d_in[8], *wme1 = (const float*)d_in[9];
    const float* wes1 = (const float*)d_in[10], *wed1 = (const float*)d_in[11];
    const float* wee1 = (const float*)d_in[12], *be1 = (const float*)d_in[13];
    const float* ws2 = (const float*)d_in[14], *bs2 = (const float*)d_in[15];
    const float* wmx2 = (const float*)d_in[16], *wme2 = (const float*)d_in[17];
    const float* wes2 = (const float*)d_in[18], *wed2 = (const float*)d_in[19];
    const float* wee2 = (const float*)d_in[20], *be2 = (const float*)d_in[21];
    const float* ws3 = (const float*)d_in[22], *bs3 = (const float*)d_in[23];
    const float* wmx3 = (const float*)d_in[24], *wme3 = (const float*)d_in[25];
    float* out = (float*)d_out;
    int n_graphs = out_size / 256;

    float *Acat, *W1n, *Wpsd, *Wq, *W2n, *W2e, *W3;
    float *x1r, *psd, *e1r, *x2r, *e2r;
    int *nX1, *nX2, *eE1;
    cudaGetSymbolAddress((void**)&Acat, g_Acat);
    cudaGetSymbolAddress((void**)&W1n,  g_W1n);
    cudaGetSymbolAddress((void**)&Wpsd, g_Wpsd);
    cudaGetSymbolAddress((void**)&Wq,   g_Wq);
    cudaGetSymbolAddress((void**)&W2n,  g_W2n);
    cudaGetSymbolAddress((void**)&W2e,  g_W2e);
    cudaGetSymbolAddress((void**)&W3,   g_W3);
    cudaGetSymbolAddress((void**)&x1r,  g_x1r);
    cudaGetSymbolAddress((void**)&psd,  g_psd);
    cudaGetSymbolAddress((void**)&e1r,  g_e1r);
    cudaGetSymbolAddress((void**)&x2r,  g_x2r);
    cudaGetSymbolAddress((void**)&e2r,  g_e2r);
    cudaGetSymbolAddress((void**)&nX1,  g_nX1);
    cudaGetSymbolAddress((void**)&nX2,  g_nX2);
    cudaGetSymbolAddress((void**)&eE1,  g_eListE1);

    const int NB_N = (NN + 255) / 256;
    const int NB_E = EE / 256;
    const int NB_A = (KA_TOTAL + 255) / 256;
    const int* nil = (const int*)0;

    kA<<<NB_A, 256>>>(batch, n_graphs, wproj, bproj,
                      ws1, bs1, wmx1, wme1, wes1, wed1, wee1, be1,
                      ws2, bs2, wmx2, wme2, wes2, wed2, wee2, be2,
                      ws3, bs3, wmx3, wme3);
    k_passA<<<NB_E, 256>>>(src, dst);
    k_passB<<<NB_E, 256>>>(src, dst);
    k_compactN<<<NB_N, 256>>>();
    k_passC<<<NB_E, 256>>>(dst);
    k_scan<<<1, 1024>>>();
    k_fill<<<NB_E, 256>>>(dst);

    // layer 1
    k_agg1<<<2048, 256>>>(x, ea, src);
    k_gemm<KP1, 128, true,  0, false><<<224, 256>>>(Acat, KP1, nil, W1n,  x1r, nX1, 4, ACAP, src, dst);
    k_gemm<256, 128, false, 0, false><<<224, 256>>>(Acat, KP1, nil, Wpsd, psd, nX1, 4, ACAP, src, dst);
    k_gemm<128,  64, false, 0, true ><<<256, 256>>>(ea,   128, eE1, Wq,   e1r, nil, 1, ACAP, src, dst);

    // layer 2
    k_scatter2<<<256, 256>>>(src, dst);
    k_gemm<KP2, 128, true, 1, false><<<16, 256>>>(nullptr, 0, nil, W2n, x2r, nX2, 5, ACAP, src, dst);
    k_gemm<KP2,  64, true, 2, false><<<16, 256>>>(nullptr, 0, nil, W2e, e2r, nil, 3, E2CAP, src, dst);

    // layer 3 + output
    k_scatter3<<<64, 256>>>(src, dst);
    k_gemm<KP2, 256, false, 3, false><<<1, 256>>>(nullptr, 0, nil, W3, out, nil, 6, NGMAX, src, dst);
}